// round 15
// baseline (speedup 1.0000x reference)
#include <cuda_runtime.h>
#include <cuda_bf16.h>

#define LATENT   16
#define NREP     10
#define NSTEPS   10
#define NLIB     169
#define DT_F     0.01f

#define SEL_LO 0x1010u   // duplicate low bf16 half
#define SEL_HI 0x3232u   // duplicate high bf16 half

__device__ __forceinline__ unsigned long long pack2u(unsigned lo, unsigned hi) {
    unsigned long long r;
    asm("mov.b64 %0, {%1, %2};" : "=l"(r) : "r"(lo), "r"(hi));
    return r;
}
__device__ __forceinline__ unsigned hfma2(unsigned a, unsigned b, unsigned c) {
    unsigned d;
    asm("fma.rn.bf16x2 %0, %1, %2, %3;" : "=r"(d) : "r"(a), "r"(b), "r"(c));
    return d;
}
__device__ __forceinline__ unsigned hmul2(unsigned a, unsigned b) {
    unsigned d;
    asm("mul.rn.bf16x2 %0, %1, %2;" : "=r"(d) : "r"(a), "r"(b));
    return d;
}
__device__ __forceinline__ unsigned prmt(unsigned a, unsigned sel) {
    unsigned d;
    asm("prmt.b32 %0, %1, %1, %2;" : "=r"(d) : "r"(a), "r"(sel));
    return d;
}
#define CVT2(dst, lo, hi) \
    asm("cvt.rn.bf16x2.f32 %0, %1, %2;" : "=r"(dst) : "f"(hi), "f"(lo))

__device__ __forceinline__ float bf16lo_f(unsigned v) { return __uint_as_float(v << 16); }
__device__ __forceinline__ float bf16hi_f(unsigned v) { return __uint_as_float(v & 0xFFFF0000u); }

// The 477us (128,4) winner with ONE change: the quadratic loops are FULLY
// UNROLLED. All 136 row indices become compile-time constants -> LDS with
// immediate offsets (no IADD address math, no loop branches) and ptxas can
// hoist coefficient loads many rows ahead of their HFMA2 consumers,
// attacking the ~20% fma-pipe idle caused by exposed LDS latency chains.
__global__ __launch_bounds__(128, 4)
void sindy_shred_kernel(const float* __restrict__ h_t,
                        const float* __restrict__ coeff,
                        const float* __restrict__ mask,
                        float* __restrict__ out,
                        int n_total)
{
    __shared__ __align__(16) unsigned long long C4[NLIB * 4];

    const int r = blockIdx.y;
    {
        const float* cr = coeff + (size_t)r * NLIB * LATENT;
        const float* mr = mask  + (size_t)r * NLIB * LATENT;
        for (int idx = threadIdx.x; idx < NLIB * 4; idx += blockDim.x) {
            int base = idx * 4;
            float c0 = cr[base + 0] * mr[base + 0];
            float c1 = cr[base + 1] * mr[base + 1];
            float c2 = cr[base + 2] * mr[base + 2];
            float c3 = cr[base + 3] * mr[base + 3];
            unsigned plo, phi;
            CVT2(plo, c0, c1);
            CVT2(phi, c2, c3);
            C4[idx] = pack2u(plo, phi);
        }
    }
    __syncthreads();

    const int n0 = blockIdx.x * 384 + threadIdx.x;   // 3 samples/thread
    const int n1 = n0 + 128;
    const int n2 = n0 + 256;
    const bool v1 = (n1 < n_total);
    const bool v2 = (n2 < n_total);
    if (n0 >= n_total) return;

    float z0[LATENT], z1[LATENT], z2[LATENT];
    {
        const float4* p0 = reinterpret_cast<const float4*>(h_t + (size_t)n0 * LATENT);
        #pragma unroll
        for (int k = 0; k < 4; k++) {
            float4 v = p0[k];
            z0[4*k+0] = v.x; z0[4*k+1] = v.y; z0[4*k+2] = v.z; z0[4*k+3] = v.w;
        }
        if (v1) {
            const float4* p1 = reinterpret_cast<const float4*>(h_t + (size_t)n1 * LATENT);
            #pragma unroll
            for (int k = 0; k < 4; k++) {
                float4 v = p1[k];
                z1[4*k+0] = v.x; z1[4*k+1] = v.y; z1[4*k+2] = v.z; z1[4*k+3] = v.w;
            }
        } else {
            #pragma unroll
            for (int k = 0; k < LATENT; k++) z1[k] = 0.0f;
        }
        if (v2) {
            const float4* p2 = reinterpret_cast<const float4*>(h_t + (size_t)n2 * LATENT);
            #pragma unroll
            for (int k = 0; k < 4; k++) {
                float4 v = p2[k];
                z2[4*k+0] = v.x; z2[4*k+1] = v.y; z2[4*k+2] = v.z; z2[4*k+3] = v.w;
            }
        } else {
            #pragma unroll
            for (int k = 0; k < LATENT; k++) z2[k] = 0.0f;
        }
    }

    #pragma unroll 1
    for (int step = 0; step < NSTEPS; step++) {
        unsigned zp0[8], zp1[8], zp2[8];
        #pragma unroll
        for (int m = 0; m < 8; m++) {
            CVT2(zp0[m], z0[2*m], z0[2*m+1]);
            CVT2(zp1[m], z1[2*m], z1[2*m+1]);
            CVT2(zp2[m], z2[2*m], z2[2*m+1]);
        }

        unsigned acc0[8], acc1[8], acc2[8];
        #pragma unroll
        for (int m = 0; m < 4; m++) {
            unsigned long long c = C4[m];
            unsigned clo = (unsigned)c, chi = (unsigned)(c >> 32);
            acc0[2*m] = clo; acc0[2*m+1] = chi;
            acc1[2*m] = clo; acc1[2*m+1] = chi;
            acc2[2*m] = clo; acc2[2*m+1] = chi;
        }

        #define ROW_OP(l, t0, t1, t2) do {                                     \
            const unsigned long long* row_ = &C4[(l) * 4];                     \
            _Pragma("unroll")                                                  \
            for (int m = 0; m < 4; m++) {                                      \
                unsigned long long cc = row_[m];                               \
                unsigned clo = (unsigned)cc, chi = (unsigned)(cc >> 32);       \
                acc0[2*m]   = hfma2((t0), clo, acc0[2*m]);                     \
                acc0[2*m+1] = hfma2((t0), chi, acc0[2*m+1]);                   \
                acc1[2*m]   = hfma2((t1), clo, acc1[2*m]);                     \
                acc1[2*m+1] = hfma2((t1), chi, acc1[2*m+1]);                   \
                acc2[2*m]   = hfma2((t2), clo, acc2[2*m]);                     \
                acc2[2*m+1] = hfma2((t2), chi, acc2[2*m+1]);                   \
            }                                                                  \
        } while (0)

        // Linear rows 1..16
        {
            int l = 1;
            #pragma unroll
            for (int m = 0; m < 8; m++) {
                unsigned t0 = prmt(zp0[m], SEL_LO);
                unsigned t1 = prmt(zp1[m], SEL_LO);
                unsigned t2 = prmt(zp2[m], SEL_LO);
                ROW_OP(l, t0, t1, t2); l++;
                t0 = prmt(zp0[m], SEL_HI);
                t1 = prmt(zp1[m], SEL_HI);
                t2 = prmt(zp2[m], SEL_HI);
                ROW_OP(l, t0, t1, t2); l++;
            }
        }

        // Quadratic rows 17..152 — FULLY UNROLLED (compile-time l)
        {
            int l = 1 + LATENT;
            #pragma unroll
            for (int i = 0; i < LATENT; i++) {
                unsigned sel = (i & 1) ? SEL_HI : SEL_LO;
                unsigned zi0 = prmt(zp0[i >> 1], sel);
                unsigned zi1 = prmt(zp1[i >> 1], sel);
                unsigned zi2 = prmt(zp2[i >> 1], sel);
                {
                    const int m = i >> 1;
                    unsigned pp0 = hmul2(zi0, zp0[m]);
                    unsigned pp1 = hmul2(zi1, zp1[m]);
                    unsigned pp2 = hmul2(zi2, zp2[m]);
                    if (!(i & 1)) {
                        ROW_OP(l, prmt(pp0, SEL_LO), prmt(pp1, SEL_LO), prmt(pp2, SEL_LO));
                        l++;
                    }
                    ROW_OP(l, prmt(pp0, SEL_HI), prmt(pp1, SEL_HI), prmt(pp2, SEL_HI));
                    l++;
                }
                #pragma unroll
                for (int m = (i >> 1) + 1; m < 8; m++) {
                    unsigned pp0 = hmul2(zi0, zp0[m]);
                    unsigned pp1 = hmul2(zi1, zp1[m]);
                    unsigned pp2 = hmul2(zi2, zp2[m]);
                    ROW_OP(l, prmt(pp0, SEL_LO), prmt(pp1, SEL_LO), prmt(pp2, SEL_LO));
                    l++;
                    ROW_OP(l, prmt(pp0, SEL_HI), prmt(pp1, SEL_HI), prmt(pp2, SEL_HI));
                    l++;
                }
            }
        }

        // Sine rows 153..168 (inline)
        {
            int l = 153;
            #pragma unroll 2
            for (int m = 0; m < 8; m++) {
                unsigned s0, s1, s2;
                CVT2(s0, __sinf(z0[2*m]), __sinf(z0[2*m+1]));
                CVT2(s1, __sinf(z1[2*m]), __sinf(z1[2*m+1]));
                CVT2(s2, __sinf(z2[2*m]), __sinf(z2[2*m+1]));
                ROW_OP(l, prmt(s0, SEL_LO), prmt(s1, SEL_LO), prmt(s2, SEL_LO));
                l++;
                ROW_OP(l, prmt(s0, SEL_HI), prmt(s1, SEL_HI), prmt(s2, SEL_HI));
                l++;
            }
        }
        #undef ROW_OP

        // Euler: z += dz * DT
        #pragma unroll
        for (int q = 0; q < 8; q++) {
            z0[2*q+0] = fmaf(bf16lo_f(acc0[q]), DT_F, z0[2*q+0]);
            z0[2*q+1] = fmaf(bf16hi_f(acc0[q]), DT_F, z0[2*q+1]);
            z1[2*q+0] = fmaf(bf16lo_f(acc1[q]), DT_F, z1[2*q+0]);
            z1[2*q+1] = fmaf(bf16hi_f(acc1[q]), DT_F, z1[2*q+1]);
            z2[2*q+0] = fmaf(bf16lo_f(acc2[q]), DT_F, z2[2*q+0]);
            z2[2*q+1] = fmaf(bf16hi_f(acc2[q]), DT_F, z2[2*q+1]);
        }
    }

    {
        float4* po = reinterpret_cast<float4*>(out + ((size_t)n0 * NREP + r) * LATENT);
        #pragma unroll
        for (int k = 0; k < 4; k++)
            po[k] = make_float4(z0[4*k+0], z0[4*k+1], z0[4*k+2], z0[4*k+3]);
        if (v1) {
            float4* p1 = reinterpret_cast<float4*>(out + ((size_t)n1 * NREP + r) * LATENT);
            #pragma unroll
            for (int k = 0; k < 4; k++)
                p1[k] = make_float4(z1[4*k+0], z1[4*k+1], z1[4*k+2], z1[4*k+3]);
        }
        if (v2) {
            float4* p2 = reinterpret_cast<float4*>(out + ((size_t)n2 * NREP + r) * LATENT);
            #pragma unroll
            for (int k = 0; k < 4; k++)
                p2[k] = make_float4(z2[4*k+0], z2[4*k+1], z2[4*k+2], z2[4*k+3]);
        }
    }
}

extern "C" void kernel_launch(void* const* d_in, const int* in_sizes, int n_in,
                              void* d_out, int out_size)
{
    const float* h_t   = (const float*)d_in[0];   // [50000, 16]
    const float* coeff = (const float*)d_in[1];   // [10, 169, 16]
    const float* mask  = (const float*)d_in[2];   // [10, 169, 16]
    float* out = (float*)d_out;                   // [50000, 10, 16]

    int n_total = in_sizes[0] / LATENT;
    int blocks_x = (n_total + 383) / 384;
    dim3 grid((unsigned)blocks_x, NREP, 1);
    sindy_shred_kernel<<<grid, 128>>>(h_t, coeff, mask, out, n_total);
}

// round 16
// speedup vs baseline: 3.4246x; 3.4246x over previous
#include <cuda_runtime.h>
#include <cuda_bf16.h>

#define LATENT   16
#define NREP     10
#define NSTEPS   10
#define NLIB     169
#define DT_F     0.01f

#define SEL_LO 0x1010u   // duplicate low bf16 half
#define SEL_HI 0x3232u   // duplicate high bf16 half

__device__ __forceinline__ unsigned long long pack2u(unsigned lo, unsigned hi) {
    unsigned long long r;
    asm("mov.b64 %0, {%1, %2};" : "=l"(r) : "r"(lo), "r"(hi));
    return r;
}
__device__ __forceinline__ unsigned hfma2(unsigned a, unsigned b, unsigned c) {
    unsigned d;
    asm("fma.rn.bf16x2 %0, %1, %2, %3;" : "=r"(d) : "r"(a), "r"(b), "r"(c));
    return d;
}
__device__ __forceinline__ unsigned hmul2(unsigned a, unsigned b) {
    unsigned d;
    asm("mul.rn.bf16x2 %0, %1, %2;" : "=r"(d) : "r"(a), "r"(b));
    return d;
}
__device__ __forceinline__ unsigned prmt(unsigned a, unsigned sel) {
    unsigned d;
    asm("prmt.b32 %0, %1, %1, %2;" : "=r"(d) : "r"(a), "r"(sel));
    return d;
}
#define CVT2(dst, lo, hi) \
    asm("cvt.rn.bf16x2.f32 %0, %1, %2;" : "=r"(dst) : "f"(hi), "f"(lo))

__device__ __forceinline__ float bf16lo_f(unsigned v) { return __uint_as_float(v << 16); }
__device__ __forceinline__ float bf16hi_f(unsigned v) { return __uint_as_float(v & 0xFFFF0000u); }

// FINAL (locked-in R9 winner, 477.5us): three samples/thread, bf16x2 HFMA2
// contraction at the fma-pipe floor (~400us busy). Coefficients bf16x2-packed
// in shared, scalar LDS.64 reads; theta generation off the fma pipe via
// PRMT (ALU) + one HMUL2 per theta pair; sin inline via MUFU; fp32 state +
// Euler. (128,4) launch bounds -> 113 regs, the best schedule found:
// all alternatives (192/64-thread shapes, const-mem coeffs, LDS.128,
// full unroll) measured slower or spilled. rel_err 2.0e-5.
__global__ __launch_bounds__(128, 4)
void sindy_shred_kernel(const float* __restrict__ h_t,
                        const float* __restrict__ coeff,
                        const float* __restrict__ mask,
                        float* __restrict__ out,
                        int n_total)
{
    __shared__ __align__(16) unsigned long long C4[NLIB * 4];

    const int r = blockIdx.y;
    {
        const float* cr = coeff + (size_t)r * NLIB * LATENT;
        const float* mr = mask  + (size_t)r * NLIB * LATENT;
        for (int idx = threadIdx.x; idx < NLIB * 4; idx += blockDim.x) {
            int base = idx * 4;
            float c0 = cr[base + 0] * mr[base + 0];
            float c1 = cr[base + 1] * mr[base + 1];
            float c2 = cr[base + 2] * mr[base + 2];
            float c3 = cr[base + 3] * mr[base + 3];
            unsigned plo, phi;
            CVT2(plo, c0, c1);
            CVT2(phi, c2, c3);
            C4[idx] = pack2u(plo, phi);
        }
    }
    __syncthreads();

    const int n0 = blockIdx.x * 384 + threadIdx.x;   // 3 samples/thread
    const int n1 = n0 + 128;
    const int n2 = n0 + 256;
    const bool v1 = (n1 < n_total);
    const bool v2 = (n2 < n_total);
    if (n0 >= n_total) return;

    float z0[LATENT], z1[LATENT], z2[LATENT];
    {
        const float4* p0 = reinterpret_cast<const float4*>(h_t + (size_t)n0 * LATENT);
        #pragma unroll
        for (int k = 0; k < 4; k++) {
            float4 v = p0[k];
            z0[4*k+0] = v.x; z0[4*k+1] = v.y; z0[4*k+2] = v.z; z0[4*k+3] = v.w;
        }
        if (v1) {
            const float4* p1 = reinterpret_cast<const float4*>(h_t + (size_t)n1 * LATENT);
            #pragma unroll
            for (int k = 0; k < 4; k++) {
                float4 v = p1[k];
                z1[4*k+0] = v.x; z1[4*k+1] = v.y; z1[4*k+2] = v.z; z1[4*k+3] = v.w;
            }
        } else {
            #pragma unroll
            for (int k = 0; k < LATENT; k++) z1[k] = 0.0f;
        }
        if (v2) {
            const float4* p2 = reinterpret_cast<const float4*>(h_t + (size_t)n2 * LATENT);
            #pragma unroll
            for (int k = 0; k < 4; k++) {
                float4 v = p2[k];
                z2[4*k+0] = v.x; z2[4*k+1] = v.y; z2[4*k+2] = v.z; z2[4*k+3] = v.w;
            }
        } else {
            #pragma unroll
            for (int k = 0; k < LATENT; k++) z2[k] = 0.0f;
        }
    }

    for (int step = 0; step < NSTEPS; step++) {
        unsigned zp0[8], zp1[8], zp2[8];
        #pragma unroll
        for (int m = 0; m < 8; m++) {
            CVT2(zp0[m], z0[2*m], z0[2*m+1]);
            CVT2(zp1[m], z1[2*m], z1[2*m+1]);
            CVT2(zp2[m], z2[2*m], z2[2*m+1]);
        }

        unsigned acc0[8], acc1[8], acc2[8];
        #pragma unroll
        for (int m = 0; m < 4; m++) {
            unsigned long long c = C4[m];
            unsigned clo = (unsigned)c, chi = (unsigned)(c >> 32);
            acc0[2*m] = clo; acc0[2*m+1] = chi;
            acc1[2*m] = clo; acc1[2*m+1] = chi;
            acc2[2*m] = clo; acc2[2*m+1] = chi;
        }

        #define ROW_OP(l, t0, t1, t2) do {                                     \
            const unsigned long long* row_ = &C4[(l) * 4];                     \
            _Pragma("unroll")                                                  \
            for (int m = 0; m < 4; m++) {                                      \
                unsigned long long cc = row_[m];                               \
                unsigned clo = (unsigned)cc, chi = (unsigned)(cc >> 32);       \
                acc0[2*m]   = hfma2((t0), clo, acc0[2*m]);                     \
                acc0[2*m+1] = hfma2((t0), chi, acc0[2*m+1]);                   \
                acc1[2*m]   = hfma2((t1), clo, acc1[2*m]);                     \
                acc1[2*m+1] = hfma2((t1), chi, acc1[2*m+1]);                   \
                acc2[2*m]   = hfma2((t2), clo, acc2[2*m]);                     \
                acc2[2*m+1] = hfma2((t2), chi, acc2[2*m+1]);                   \
            }                                                                  \
        } while (0)

        // Linear rows 1..16
        {
            int l = 1;
            #pragma unroll 2
            for (int m = 0; m < 8; m++) {
                unsigned t0 = prmt(zp0[m], SEL_LO);
                unsigned t1 = prmt(zp1[m], SEL_LO);
                unsigned t2 = prmt(zp2[m], SEL_LO);
                ROW_OP(l, t0, t1, t2); l++;
                t0 = prmt(zp0[m], SEL_HI);
                t1 = prmt(zp1[m], SEL_HI);
                t2 = prmt(zp2[m], SEL_HI);
                ROW_OP(l, t0, t1, t2); l++;
            }
        }

        // Quadratic rows 17..152 (runtime loops: the register-safe structure)
        {
            int l = 1 + LATENT;
            for (int i = 0; i < LATENT; i++) {
                unsigned sel = (i & 1) ? SEL_HI : SEL_LO;
                unsigned zi0 = prmt(zp0[i >> 1], sel);
                unsigned zi1 = prmt(zp1[i >> 1], sel);
                unsigned zi2 = prmt(zp2[i >> 1], sel);
                int m = i >> 1;
                {
                    unsigned pp0 = hmul2(zi0, zp0[m]);
                    unsigned pp1 = hmul2(zi1, zp1[m]);
                    unsigned pp2 = hmul2(zi2, zp2[m]);
                    if (!(i & 1)) {
                        ROW_OP(l, prmt(pp0, SEL_LO), prmt(pp1, SEL_LO), prmt(pp2, SEL_LO));
                        l++;
                    }
                    ROW_OP(l, prmt(pp0, SEL_HI), prmt(pp1, SEL_HI), prmt(pp2, SEL_HI));
                    l++;
                }
                for (m = (i >> 1) + 1; m < 8; m++) {
                    unsigned pp0 = hmul2(zi0, zp0[m]);
                    unsigned pp1 = hmul2(zi1, zp1[m]);
                    unsigned pp2 = hmul2(zi2, zp2[m]);
                    ROW_OP(l, prmt(pp0, SEL_LO), prmt(pp1, SEL_LO), prmt(pp2, SEL_LO));
                    l++;
                    ROW_OP(l, prmt(pp0, SEL_HI), prmt(pp1, SEL_HI), prmt(pp2, SEL_HI));
                    l++;
                }
            }
        }

        // Sine rows 153..168 (inline, no persistent arrays)
        {
            int l = 153;
            #pragma unroll 2
            for (int m = 0; m < 8; m++) {
                unsigned s0, s1, s2;
                CVT2(s0, __sinf(z0[2*m]), __sinf(z0[2*m+1]));
                CVT2(s1, __sinf(z1[2*m]), __sinf(z1[2*m+1]));
                CVT2(s2, __sinf(z2[2*m]), __sinf(z2[2*m+1]));
                ROW_OP(l, prmt(s0, SEL_LO), prmt(s1, SEL_LO), prmt(s2, SEL_LO));
                l++;
                ROW_OP(l, prmt(s0, SEL_HI), prmt(s1, SEL_HI), prmt(s2, SEL_HI));
                l++;
            }
        }
        #undef ROW_OP

        // Euler: z += dz * DT
        #pragma unroll
        for (int q = 0; q < 8; q++) {
            z0[2*q+0] = fmaf(bf16lo_f(acc0[q]), DT_F, z0[2*q+0]);
            z0[2*q+1] = fmaf(bf16hi_f(acc0[q]), DT_F, z0[2*q+1]);
            z1[2*q+0] = fmaf(bf16lo_f(acc1[q]), DT_F, z1[2*q+0]);
            z1[2*q+1] = fmaf(bf16hi_f(acc1[q]), DT_F, z1[2*q+1]);
            z2[2*q+0] = fmaf(bf16lo_f(acc2[q]), DT_F, z2[2*q+0]);
            z2[2*q+1] = fmaf(bf16hi_f(acc2[q]), DT_F, z2[2*q+1]);
        }
    }

    {
        float4* po = reinterpret_cast<float4*>(out + ((size_t)n0 * NREP + r) * LATENT);
        #pragma unroll
        for (int k = 0; k < 4; k++)
            po[k] = make_float4(z0[4*k+0], z0[4*k+1], z0[4*k+2], z0[4*k+3]);
        if (v1) {
            float4* p1 = reinterpret_cast<float4*>(out + ((size_t)n1 * NREP + r) * LATENT);
            #pragma unroll
            for (int k = 0; k < 4; k++)
                p1[k] = make_float4(z1[4*k+0], z1[4*k+1], z1[4*k+2], z1[4*k+3]);
        }
        if (v2) {
            float4* p2 = reinterpret_cast<float4*>(out + ((size_t)n2 * NREP + r) * LATENT);
            #pragma unroll
            for (int k = 0; k < 4; k++)
                p2[k] = make_float4(z2[4*k+0], z2[4*k+1], z2[4*k+2], z2[4*k+3]);
        }
    }
}

extern "C" void kernel_launch(void* const* d_in, const int* in_sizes, int n_in,
                              void* d_out, int out_size)
{
    const float* h_t   = (const float*)d_in[0];   // [50000, 16]
    const float* coeff = (const float*)d_in[1];   // [10, 169, 16]
    const float* mask  = (const float*)d_in[2];   // [10, 169, 16]
    float* out = (float*)d_out;                   // [50000, 10, 16]

    int n_total = in_sizes[0] / LATENT;
    int blocks_x = (n_total + 383) / 384;
    dim3 grid((unsigned)blocks_x, NREP, 1);
    sindy_shred_kernel<<<grid, 128>>>(h_t, coeff, mask, out, n_total);
}